// round 10
// baseline (speedup 1.0000x reference)
#include <cuda_runtime.h>
#include <cuda.h>
#include <cstdint>

#define NB 2
#define NH 12
#define SQ 2048
#define DH 64
#define DM 768
#define SCALE 0.125f

// Scratch for Q/K/V in [B, H, S, Dh] layout (device globals: allocation-free rule)
__device__ float g_q[NB * NH * SQ * DH];
__device__ float g_k[NB * NH * SQ * DH];
__device__ float g_v[NB * NH * SQ * DH];

__device__ __forceinline__ uint32_t f2tf(float f) {
    uint32_t u;
    asm("cvt.rna.tf32.f32 %0, %1;" : "=r"(u) : "f"(f));
    return u;
}

__device__ __forceinline__ uint4 cvt4(float4 v) {
    return make_uint4(f2tf(v.x), f2tf(v.y), f2tf(v.z), f2tf(v.w));
}

__device__ __forceinline__ void mma8(float* c, const uint32_t* a, const uint32_t* b) {
    asm volatile(
        "mma.sync.aligned.m16n8k8.row.col.f32.tf32.tf32.f32 "
        "{%0,%1,%2,%3}, {%4,%5,%6,%7}, {%8,%9}, {%0,%1,%2,%3};\n"
        : "+f"(c[0]), "+f"(c[1]), "+f"(c[2]), "+f"(c[3])
        : "r"(a[0]), "r"(a[1]), "r"(a[2]), "r"(a[3]), "r"(b[0]), "r"(b[1]));
}

// word-index swizzle inside a SW128 tile with 128B rows (32 f32 words/row)
#define SWZ(r, c) ((r) * 32 + ((c) ^ (4 * ((r) & 7))))

__device__ __forceinline__ void tma_load_2d(uint32_t dst, const CUtensorMap* map,
                                            int cx, int cy, uint32_t mbar) {
    asm volatile(
        "cp.async.bulk.tensor.2d.shared::cta.global.tile.mbarrier::complete_tx::bytes "
        "[%0], [%1, {%2, %3}], [%4];"
        :: "r"(dst), "l"(map), "r"(cx), "r"(cy), "r"(mbar) : "memory");
}

// ---------------------------------------------------------------------------
// Kernel 1: fused QKV projection (unchanged R5 version).
// ---------------------------------------------------------------------------
__global__ __launch_bounds__(256) void qkv_kernel(
    const float* __restrict__ X,
    const float* __restrict__ Wq, const float* __restrict__ bq,
    const float* __restrict__ Wk, const float* __restrict__ bk,
    const float* __restrict__ Wv, const float* __restrict__ bv)
{
    const float* W;
    const float* bias;
    float* out;
    if (blockIdx.z == 0)      { W = Wq; bias = bq; out = g_q; }
    else if (blockIdx.z == 1) { W = Wk; bias = bk; out = g_k; }
    else                      { W = Wv; bias = bv; out = g_v; }

    __shared__ uint32_t As[128][36];
    __shared__ uint32_t Bs[64][36];

    const int tid  = threadIdx.x;
    const int lane = tid & 31;
    const int warp = tid >> 5;
    const int wm   = warp >> 1;
    const int wn   = warp & 1;
    const int m0   = blockIdx.y * 128;
    const int n0   = blockIdx.x * 64;

    float acc[2][4][4];
    #pragma unroll
    for (int i = 0; i < 2; i++)
        #pragma unroll
        for (int j = 0; j < 4; j++)
            #pragma unroll
            for (int e = 0; e < 4; e++) acc[i][j][e] = 0.f;

    const int ar = tid >> 3;
    const int ac = (tid & 7) * 4;

    for (int kt = 0; kt < DM / 32; kt++) {
        const int k0 = kt * 32;
        #pragma unroll
        for (int it = 0; it < 4; it++) {
            int r = ar + it * 32;
            float4 v = *(const float4*)&X[(size_t)(m0 + r) * DM + k0 + ac];
            *(uint4*)&As[r][ac] = cvt4(v);
        }
        #pragma unroll
        for (int it = 0; it < 2; it++) {
            int r = ar + it * 32;
            float4 v = *(const float4*)&W[(size_t)(n0 + r) * DM + k0 + ac];
            *(uint4*)&Bs[r][ac] = cvt4(v);
        }
        __syncthreads();
        #pragma unroll
        for (int kk = 0; kk < 4; kk++) {
            uint32_t a[2][4], b[4][2];
            #pragma unroll
            for (int i = 0; i < 2; i++) {
                int r = wm * 32 + i * 16 + (lane >> 2);
                int c = kk * 8 + (lane & 3);
                a[i][0] = As[r][c];
                a[i][1] = As[r + 8][c];
                a[i][2] = As[r][c + 4];
                a[i][3] = As[r + 8][c + 4];
            }
            #pragma unroll
            for (int j = 0; j < 4; j++) {
                int cc = wn * 32 + j * 8 + (lane >> 2);
                int c  = kk * 8 + (lane & 3);
                b[j][0] = Bs[cc][c];
                b[j][1] = Bs[cc][c + 4];
            }
            #pragma unroll
            for (int i = 0; i < 2; i++)
                #pragma unroll
                for (int j = 0; j < 4; j++)
                    mma8(acc[i][j], a[i], b[j]);
        }
        __syncthreads();
    }

    #pragma unroll
    for (int i = 0; i < 2; i++) {
        #pragma unroll
        for (int j = 0; j < 4; j++) {
            int n  = n0 + wn * 32 + j * 8 + 2 * (lane & 3);
            int h  = n >> 6;
            int dh = n & 63;
            float b0 = bias[n], b1 = bias[n + 1];
            #pragma unroll
            for (int rr = 0; rr < 2; rr++) {
                int m  = m0 + wm * 32 + i * 16 + (lane >> 2) + rr * 8;
                int bb = m >> 11;
                int s  = m & 2047;
                size_t idx = (((size_t)(bb * NH + h)) * SQ + s) * DH + dh;
                out[idx]     = acc[i][j][rr * 2 + 0] + b0;
                out[idx + 1] = acc[i][j][rr * 2 + 1] + b1;
            }
        }
    }
}

// ---------------------------------------------------------------------------
// Kernel 2: flash attention + RealFormer residual (R8 structure).
// CHANGE vs R8: after the TMA mbarrier wait, an IN-PLACE convert pass turns
// the K/V tiles into tf32 bits ONCE (pointwise -> swizzle-agnostic; 8 LDS.128
// + 32 cvt + 8 STS.128 per thread, conflict-free). QK/PV fragment reads then
// consume raw bits with NO per-use cvt (-128 cvt/thread/chunk). Operand bits
// identical to R8 -> bitwise-same results.
// Single-buffer TMA, one mbarrier, static smem, 4 CTAs/SM (exactly R8).
// ---------------------------------------------------------------------------
__global__ __launch_bounds__(128, 4) void attn_kernel(
    const __grid_constant__ CUtensorMap mapK,
    const __grid_constant__ CUtensorMap mapV,
    const __grid_constant__ CUtensorMap mapR,
    const float* __restrict__ mask,
    float* __restrict__ ctx_out,
    float* __restrict__ res_out)
{
    __shared__ __align__(1024) float sK2[2][1024];   // two [32 key x 32 dh] SW128 tiles
    __shared__ __align__(1024) float sV2[2][1024];   // two [32 key x 32 dh] SW128 tiles
    __shared__ __align__(1024) float sR[2048];       // [64 q x 32 k] SW128 tile
    __shared__ uint64_t mbar;

    const int tid  = threadIdx.x;
    const int lane = tid & 31;
    const int warp = tid >> 5;          // 0..3
    const int q4   = lane & 3;
    const int r4   = lane >> 2;
    const int h  = blockIdx.y;
    const int b  = blockIdx.z;
    const int bh = b * NH + h;
    const int q0 = blockIdx.x * 64;

    const uint32_t mb = (uint32_t)__cvta_generic_to_shared(&mbar);
    const uint32_t sK0a = (uint32_t)__cvta_generic_to_shared(&sK2[0][0]);
    const uint32_t sK1a = (uint32_t)__cvta_generic_to_shared(&sK2[1][0]);
    const uint32_t sV0a = (uint32_t)__cvta_generic_to_shared(&sV2[0][0]);
    const uint32_t sV1a = (uint32_t)__cvta_generic_to_shared(&sV2[1][0]);
    const uint32_t sRa  = (uint32_t)__cvta_generic_to_shared(&sR[0]);

    if (tid == 0) {
        asm volatile("mbarrier.init.shared.b64 [%0], 1;" :: "r"(mb) : "memory");
    }
    __syncthreads();

    const float* Q = g_q + (size_t)bh * SQ * DH;

    // Q fragments (standard m16n8k8 A layout: k cols q4, q4+4 per group of 8)
    uint32_t qf[8][4];
    {
        int r0 = q0 + warp * 16 + r4;
        const float* Qr0 = Q + (size_t)r0 * DH;
        const float* Qr8 = Qr0 + 8 * DH;
        #pragma unroll
        for (int kk = 0; kk < 8; kk++) {
            int c = kk * 8 + q4;
            qf[kk][0] = f2tf(Qr0[c]);
            qf[kk][1] = f2tf(Qr8[c]);
            qf[kk][2] = f2tf(Qr0[c + 4]);
            qf[kk][3] = f2tf(Qr8[c + 4]);
        }
    }

    float Oacc[8][4];
    #pragma unroll
    for (int f = 0; f < 8; f++)
        #pragma unroll
        for (int e = 0; e < 4; e++) Oacc[f][e] = 0.f;
    float mrow0 = -1e30f, mrow1 = -1e30f;
    float lrow0 = 0.f, lrow1 = 0.f;

    const int rq0 = q0 + warp * 16 + r4;
    const size_t res0 = ((size_t)bh * SQ + rq0) * SQ;
    const size_t res8 = res0 + (size_t)8 * SQ;
    const float* mrk = mask + b * SQ;
    const int lr0 = warp * 16 + r4;     // local row in sR

    for (int j = 0; j < SQ / 32; j++) {
        const int kb = j * 32;
        __syncthreads();   // all warps done reading previous chunk's tiles

        if (tid == 0) {
            const int rowKV = bh * SQ + kb;
            asm volatile("mbarrier.arrive.expect_tx.shared.b64 _, [%0], %1;"
                         :: "r"(mb), "r"(24576u) : "memory");
            tma_load_2d(sK0a, &mapK, 0,  rowKV, mb);
            tma_load_2d(sK1a, &mapK, 32, rowKV, mb);
            tma_load_2d(sV0a, &mapV, 0,  rowKV, mb);
            tma_load_2d(sV1a, &mapV, 32, rowKV, mb);
            tma_load_2d(sRa,  &mapR, kb, bh * SQ + q0, mb);
        }
        // wait for TMA completion (phase parity = j & 1)
        {
            uint32_t ph = (uint32_t)(j & 1);
            asm volatile(
                "{\n\t"
                ".reg .pred P;\n\t"
                "WL%=:\n\t"
                "mbarrier.try_wait.parity.acquire.cta.shared::cta.b64 P, [%0], %1, 0x989680;\n\t"
                "@P bra WD%=;\n\t"
                "bra WL%=;\n\t"
                "WD%=:\n\t"
                "}"
                :: "r"(mb), "r"(ph) : "memory");
        }

        // In-place convert pass: K/V tiles f32 -> tf32 bits, once per element.
        // Pointwise, so swizzle-agnostic. 16B per lane: conflict-free.
        {
            float4* pk = (float4*)sK2;      // 512 float4
            float4* pv = (float4*)sV2;      // 512 float4
            #pragma unroll
            for (int it = 0; it < 4; it++) {
                int i = tid + it * 128;
                float4 kv = pk[i];
                ((uint4*)pk)[i] = cvt4(kv);
                float4 vv = pv[i];
                ((uint4*)pv)[i] = cvt4(vv);
            }
        }
        __syncthreads();

        // S = Q . K^T  (m16 x n32, k=64); K frags are raw tf32 bits, no cvt
        float s[4][4];
        #pragma unroll
        for (int f = 0; f < 4; f++)
            #pragma unroll
            for (int e = 0; e < 4; e++) s[f][e] = 0.f;
        #pragma unroll
        for (int kk = 0; kk < 8; kk++) {
            const uint32_t* kbase = (const uint32_t*)sK2[kk >> 2];
            const int c32 = (kk & 3) * 8 + q4;
            #pragma unroll
            for (int f = 0; f < 4; f++) {
                int key = f * 8 + r4;
                uint32_t b2[2] = { kbase[SWZ(key, c32)],
                                   kbase[SWZ(key, c32 + 4)] };
                mma8(s[f], qf[kk], b2);
            }
        }

        // scale + residual (LDS from TMA tile), write res_out pre-mask, + mask
        #pragma unroll
        for (int f = 0; f < 4; f++) {
            int c = f * 8 + 2 * q4;
            float2 r0v = *(const float2*)&sR[SWZ(lr0, c)];
            float2 r8v = *(const float2*)&sR[SWZ(lr0 + 8, c)];
            s[f][0] = s[f][0] * SCALE + r0v.x;
            s[f][1] = s[f][1] * SCALE + r0v.y;
            s[f][2] = s[f][2] * SCALE + r8v.x;
            s[f][3] = s[f][3] * SCALE + r8v.y;
            int col = kb + c;
            __stcs((float2*)&res_out[res0 + col], make_float2(s[f][0], s[f][1]));
            __stcs((float2*)&res_out[res8 + col], make_float2(s[f][2], s[f][3]));
            float2 mk = *(const float2*)&mrk[col];
            s[f][0] += mk.x; s[f][1] += mk.y;
            s[f][2] += mk.x; s[f][3] += mk.y;
        }

        // online softmax (rows within a quad: shfl xor 1,2)
        float cmax0 = -1e30f, cmax1 = -1e30f;
        #pragma unroll
        for (int f = 0; f < 4; f++) {
            cmax0 = fmaxf(cmax0, fmaxf(s[f][0], s[f][1]));
            cmax1 = fmaxf(cmax1, fmaxf(s[f][2], s[f][3]));
        }
        cmax0 = fmaxf(cmax0, __shfl_xor_sync(0xffffffff, cmax0, 1));
        cmax0 = fmaxf(cmax0, __shfl_xor_sync(0xffffffff, cmax0, 2));
        cmax1 = fmaxf(cmax1, __shfl_xor_sync(0xffffffff, cmax1, 1));
        cmax1 = fmaxf(cmax1, __shfl_xor_sync(0xffffffff, cmax1, 2));
        float nm0 = fmaxf(mrow0, cmax0);
        float nm1 = fmaxf(mrow1, cmax1);
        float corr0 = __expf(mrow0 - nm0);
        float corr1 = __expf(mrow1 - nm1);
        mrow0 = nm0; mrow1 = nm1;

        float sum0 = 0.f, sum1 = 0.f;
        #pragma unroll
        for (int f = 0; f < 4; f++) {
            s[f][0] = __expf(s[f][0] - nm0);
            s[f][1] = __expf(s[f][1] - nm0);
            s[f][2] = __expf(s[f][2] - nm1);
            s[f][3] = __expf(s[f][3] - nm1);
            sum0 += s[f][0] + s[f][1];
            sum1 += s[f][2] + s[f][3];
        }
        sum0 += __shfl_xor_sync(0xffffffff, sum0, 1);
        sum0 += __shfl_xor_sync(0xffffffff, sum0, 2);
        sum1 += __shfl_xor_sync(0xffffffff, sum1, 1);
        sum1 += __shfl_xor_sync(0xffffffff, sum1, 2);
        lrow0 = lrow0 * corr0 + sum0;
        lrow1 = lrow1 * corr1 + sum1;
        #pragma unroll
        for (int f = 0; f < 8; f++) {
            Oacc[f][0] *= corr0; Oacc[f][1] *= corr0;
            Oacc[f][2] *= corr1; Oacc[f][3] *= corr1;
        }

        // O += P . V : A-frags direct from QK C regs (key-permuted to match C);
        // V frags are raw tf32 bits, no cvt
        #pragma unroll
        for (int kk = 0; kk < 4; kk++) {
            uint32_t a[4] = { f2tf(s[kk][0]), f2tf(s[kk][2]),
                              f2tf(s[kk][1]), f2tf(s[kk][3]) };
            const int kr = kk * 8 + 2 * q4;
            #pragma unroll
            for (int f = 0; f < 8; f++) {
                const uint32_t* vbase = (const uint32_t*)sV2[f >> 2];
                const int c32 = (f & 3) * 8 + r4;
                uint32_t b2[2] = { vbase[SWZ(kr, c32)],
                                   vbase[SWZ(kr + 1, c32)] };
                mma8(Oacc[f], a, b2);
            }
        }
    }

    // Epilogue: O / l, store ctx [B, S, H*Dh]
    float inv0 = 1.f / lrow0;
    float inv1 = 1.f / lrow1;
    int row0 = q0 + warp * 16 + r4;
    #pragma unroll
    for (int f = 0; f < 8; f++) {
        int dh = f * 8 + 2 * q4;
        size_t i0 = ((size_t)b * SQ + row0) * DM + h * DH + dh;
        size_t i8 = ((size_t)b * SQ + row0 + 8) * DM + h * DH + dh;
        *(float2*)&ctx_out[i0] = make_float2(Oacc[f][0] * inv0, Oacc[f][1] * inv0);
        *(float2*)&ctx_out[i8] = make_float2(Oacc[f][2] * inv1, Oacc[f][3] * inv1);
    }
}

// ---------------------------------------------------------------------------
// Host
// ---------------------------------------------------------------------------
typedef CUresult (*tEncodeTiled)(
    CUtensorMap*, CUtensorMapDataType, cuuint32_t, void*,
    const cuuint64_t*, const cuuint64_t*, const cuuint32_t*, const cuuint32_t*,
    CUtensorMapInterleave, CUtensorMapSwizzle, CUtensorMapL2promotion,
    CUtensorMapFloatOOBfill);

static void encode_2d(tEncodeTiled fn, CUtensorMap* m, void* ptr,
                      uint64_t d0, uint64_t d1, uint64_t stride1_bytes,
                      uint32_t b0, uint32_t b1) {
    cuuint64_t dims[2]    = {d0, d1};
    cuuint64_t strides[1] = {stride1_bytes};
    cuuint32_t box[2]     = {b0, b1};
    cuuint32_t es[2]      = {1, 1};
    fn(m, CU_TENSOR_MAP_DATA_TYPE_FLOAT32, 2, ptr, dims, strides, box, es,
       CU_TENSOR_MAP_INTERLEAVE_NONE, CU_TENSOR_MAP_SWIZZLE_128B,
       CU_TENSOR_MAP_L2_PROMOTION_L2_128B, CU_TENSOR_MAP_FLOAT_OOB_FILL_NONE);
}

extern "C" void kernel_launch(void* const* d_in, const int* in_sizes, int n_in,
                              void* d_out, int out_size) {
    const float* X    = (const float*)d_in[0];
    const float* mask = (const float*)d_in[1];
    const float* res  = (const float*)d_in[2];
    const float* Wq   = (const float*)d_in[3];
    const float* bq   = (const float*)d_in[4];
    const float* Wk   = (const float*)d_in[5];
    const float* bk   = (const float*)d_in[6];
    const float* Wv   = (const float*)d_in[7];
    const float* bv   = (const float*)d_in[8];

    float* ctx     = (float*)d_out;
    float* res_out = (float*)d_out + (size_t)NB * SQ * DM;

    tEncodeTiled fn = nullptr;
    cudaDriverEntryPointQueryResult qres;
    cudaGetDriverEntryPoint("cuTensorMapEncodeTiled", (void**)&fn,
                            cudaEnableDefault, &qres);

    void* gk = nullptr;
    void* gv = nullptr;
    cudaGetSymbolAddress(&gk, g_k);
    cudaGetSymbolAddress(&gv, g_v);

    CUtensorMap mk, mv, mr;
    encode_2d(fn, &mk, gk, DH, (uint64_t)NB * NH * SQ, DH * 4, 32, 32);
    encode_2d(fn, &mv, gv, DH, (uint64_t)NB * NH * SQ, DH * 4, 32, 32);
    encode_2d(fn, &mr, (void*)res, SQ, (uint64_t)NB * NH * SQ, SQ * 4, 32, 64);

    dim3 g1(DM / 64, (NB * SQ) / 128, 3);
    qkv_kernel<<<g1, 256>>>(X, Wq, bq, Wk, bk, Wv, bv);

    dim3 g2(SQ / 64, NH, NB);
    attn_kernel<<<g2, 128>>>(mk, mv, mr, mask, ctx, res_out);
}

// round 11
// speedup vs baseline: 1.4610x; 1.4610x over previous
#include <cuda_runtime.h>
#include <cuda.h>
#include <cstdint>

#define NB 2
#define NH 12
#define SQ 2048
#define DH 64
#define DM 768
#define SCALE 0.125f

// Scratch for Q/K/V in [B, H, S, Dh] layout (device globals: allocation-free rule)
__device__ float g_q[NB * NH * SQ * DH];
__device__ float g_k[NB * NH * SQ * DH];
__device__ float g_v[NB * NH * SQ * DH];

__device__ __forceinline__ uint32_t f2tf(float f) {
    uint32_t u;
    asm("cvt.rna.tf32.f32 %0, %1;" : "=r"(u) : "f"(f));
    return u;
}

__device__ __forceinline__ uint4 cvt4(float4 v) {
    return make_uint4(f2tf(v.x), f2tf(v.y), f2tf(v.z), f2tf(v.w));
}

__device__ __forceinline__ void mma8(float* c, const uint32_t* a, const uint32_t* b) {
    asm volatile(
        "mma.sync.aligned.m16n8k8.row.col.f32.tf32.tf32.f32 "
        "{%0,%1,%2,%3}, {%4,%5,%6,%7}, {%8,%9}, {%0,%1,%2,%3};\n"
        : "+f"(c[0]), "+f"(c[1]), "+f"(c[2]), "+f"(c[3])
        : "r"(a[0]), "r"(a[1]), "r"(a[2]), "r"(a[3]), "r"(b[0]), "r"(b[1]));
}

// word-index swizzle inside a SW128 tile with 128B rows (32 f32 words/row)
#define SWZ(r, c) ((r) * 32 + ((c) ^ (4 * ((r) & 7))))

__device__ __forceinline__ void tma_load_2d(uint32_t dst, const CUtensorMap* map,
                                            int cx, int cy, uint32_t mbar) {
    asm volatile(
        "cp.async.bulk.tensor.2d.shared::cta.global.tile.mbarrier::complete_tx::bytes "
        "[%0], [%1, {%2, %3}], [%4];"
        :: "r"(dst), "l"(map), "r"(cx), "r"(cy), "r"(mbar) : "memory");
}

// ---------------------------------------------------------------------------
// Kernel 1: FUSED QKV projection. One block computes Q, K, V for its
// (m-tile, n-tile): X tile loaded to smem ONCE (was 3x across z-blocks),
// 3 resident W tiles. X L2 traffic /3. 512 threads, 16 warps: warp tile
// 16x32 per output (acc 3x16 = 48 regs). Accumulation order per output
// element identical to the R5 kernel -> bitwise-same Q/K/V.
// Grid: (12 n-tiles, 32 m-tiles).
// ---------------------------------------------------------------------------
__global__ __launch_bounds__(512, 1) void qkv_kernel(
    const float* __restrict__ X,
    const float* __restrict__ Wq, const float* __restrict__ bq,
    const float* __restrict__ Wk, const float* __restrict__ bk,
    const float* __restrict__ Wv, const float* __restrict__ bv)
{
    __shared__ uint32_t As[128][36];
    __shared__ uint32_t Bs[3][64][36];

    const int tid  = threadIdx.x;
    const int lane = tid & 31;
    const int warp = tid >> 5;     // 0..15
    const int wm   = warp >> 1;    // 0..7 : 16-row subtile
    const int wn   = warp & 1;     // 0..1 : 32-col subtile
    const int m0   = blockIdx.y * 128;
    const int n0   = blockIdx.x * 64;

    const float* Ws[3] = {Wq, Wk, Wv};

    float acc[3][4][4];
    #pragma unroll
    for (int z = 0; z < 3; z++)
        #pragma unroll
        for (int j = 0; j < 4; j++)
            #pragma unroll
            for (int e = 0; e < 4; e++) acc[z][j][e] = 0.f;

    // global-load indexing: 1024 float4 for As (2/thread), 512 per Bs tile
    // (1/thread per z; unroll index it == z).
    const int ar = tid >> 3;          // 0..63
    const int ac = (tid & 7) * 4;     // 0..28

    for (int kt = 0; kt < 24; kt++) {
        const int k0 = kt * 32;
        #pragma unroll
        for (int it = 0; it < 2; it++) {
            int r = ar + it * 64;
            float4 v = *(const float4*)&X[(size_t)(m0 + r) * DM + k0 + ac];
            *(uint4*)&As[r][ac] = cvt4(v);
        }
        #pragma unroll
        for (int z = 0; z < 3; z++) {
            if (ar < 64) {
                float4 v = *(const float4*)&Ws[z][(size_t)(n0 + ar) * DM + k0 + ac];
                *(uint4*)&Bs[z][ar][ac] = cvt4(v);
            }
        }
        __syncthreads();
        #pragma unroll
        for (int kk = 0; kk < 4; kk++) {
            const int rA = wm * 16 + (lane >> 2);
            const int c  = kk * 8 + (lane & 3);
            uint32_t a[4];
            a[0] = As[rA][c];
            a[1] = As[rA + 8][c];
            a[2] = As[rA][c + 4];
            a[3] = As[rA + 8][c + 4];
            #pragma unroll
            for (int z = 0; z < 3; z++) {
                #pragma unroll
                for (int j = 0; j < 4; j++) {
                    int cc = wn * 32 + j * 8 + (lane >> 2);
                    uint32_t b2[2] = { Bs[z][cc][c], Bs[z][cc][c + 4] };
                    mma8(acc[z][j], a, b2);
                }
            }
        }
        __syncthreads();
    }

    // Epilogue: +bias, store to [B,H,S,Dh] scratch
    const float* biases[3] = {bq, bk, bv};
    float* outs[3] = {g_q, g_k, g_v};
    #pragma unroll
    for (int z = 0; z < 3; z++) {
        #pragma unroll
        for (int j = 0; j < 4; j++) {
            int n  = n0 + wn * 32 + j * 8 + 2 * (lane & 3);
            int hh = n >> 6;
            int dh = n & 63;
            float b0 = biases[z][n], b1 = biases[z][n + 1];
            #pragma unroll
            for (int rr = 0; rr < 2; rr++) {
                int m  = m0 + wm * 16 + (lane >> 2) + rr * 8;
                int bb = m >> 11;
                int s  = m & 2047;
                size_t idx = (((size_t)(bb * NH + hh)) * SQ + s) * DH + dh;
                outs[z][idx]     = acc[z][j][rr * 2 + 0] + b0;
                outs[z][idx + 1] = acc[z][j][rr * 2 + 1] + b1;
            }
        }
    }
}

// ---------------------------------------------------------------------------
// Kernel 2: flash attention + RealFormer residual — EXACT R8 (best measured:
// 341.9us). Single-buffer TMA loads of K/V/res tiles into SW128 smem (fill is
// off the L1tex wavefront path), fragments via LDS + per-use cvt, PV A-frags
// direct from QK C registers. CTA = 128 threads / 64 q-rows, 4 CTAs/SM.
// ---------------------------------------------------------------------------
__global__ __launch_bounds__(128, 4) void attn_kernel(
    const __grid_constant__ CUtensorMap mapK,
    const __grid_constant__ CUtensorMap mapV,
    const __grid_constant__ CUtensorMap mapR,
    const float* __restrict__ mask,
    float* __restrict__ ctx_out,
    float* __restrict__ res_out)
{
    __shared__ __align__(1024) float sK2[2][1024];   // two [32 key x 32 dh] SW128 tiles
    __shared__ __align__(1024) float sV2[2][1024];   // two [32 key x 32 dh] SW128 tiles
    __shared__ __align__(1024) float sR[2048];       // [64 q x 32 k] SW128 tile
    __shared__ uint64_t mbar;

    const int tid  = threadIdx.x;
    const int lane = tid & 31;
    const int warp = tid >> 5;          // 0..3
    const int q4   = lane & 3;
    const int r4   = lane >> 2;
    const int h  = blockIdx.y;
    const int b  = blockIdx.z;
    const int bh = b * NH + h;
    const int q0 = blockIdx.x * 64;

    const uint32_t mb = (uint32_t)__cvta_generic_to_shared(&mbar);
    const uint32_t sK0a = (uint32_t)__cvta_generic_to_shared(&sK2[0][0]);
    const uint32_t sK1a = (uint32_t)__cvta_generic_to_shared(&sK2[1][0]);
    const uint32_t sV0a = (uint32_t)__cvta_generic_to_shared(&sV2[0][0]);
    const uint32_t sV1a = (uint32_t)__cvta_generic_to_shared(&sV2[1][0]);
    const uint32_t sRa  = (uint32_t)__cvta_generic_to_shared(&sR[0]);

    if (tid == 0) {
        asm volatile("mbarrier.init.shared.b64 [%0], 1;" :: "r"(mb) : "memory");
    }
    __syncthreads();

    const float* Q = g_q + (size_t)bh * SQ * DH;

    // Q fragments (standard m16n8k8 A layout: k cols q4, q4+4 per group of 8)
    uint32_t qf[8][4];
    {
        int r0 = q0 + warp * 16 + r4;
        const float* Qr0 = Q + (size_t)r0 * DH;
        const float* Qr8 = Qr0 + 8 * DH;
        #pragma unroll
        for (int kk = 0; kk < 8; kk++) {
            int c = kk * 8 + q4;
            qf[kk][0] = f2tf(Qr0[c]);
            qf[kk][1] = f2tf(Qr8[c]);
            qf[kk][2] = f2tf(Qr0[c + 4]);
            qf[kk][3] = f2tf(Qr8[c + 4]);
        }
    }

    float Oacc[8][4];
    #pragma unroll
    for (int f = 0; f < 8; f++)
        #pragma unroll
        for (int e = 0; e < 4; e++) Oacc[f][e] = 0.f;
    float mrow0 = -1e30f, mrow1 = -1e30f;
    float lrow0 = 0.f, lrow1 = 0.f;

    const int rq0 = q0 + warp * 16 + r4;
    const size_t res0 = ((size_t)bh * SQ + rq0) * SQ;
    const size_t res8 = res0 + (size_t)8 * SQ;
    const float* mrk = mask + b * SQ;
    const int lr0 = warp * 16 + r4;     // local row in sR

    for (int j = 0; j < SQ / 32; j++) {
        const int kb = j * 32;
        __syncthreads();   // all warps done reading previous chunk's tiles

        if (tid == 0) {
            const int rowKV = bh * SQ + kb;
            asm volatile("mbarrier.arrive.expect_tx.shared.b64 _, [%0], %1;"
                         :: "r"(mb), "r"(24576u) : "memory");
            tma_load_2d(sK0a, &mapK, 0,  rowKV, mb);
            tma_load_2d(sK1a, &mapK, 32, rowKV, mb);
            tma_load_2d(sV0a, &mapV, 0,  rowKV, mb);
            tma_load_2d(sV1a, &mapV, 32, rowKV, mb);
            tma_load_2d(sRa,  &mapR, kb, bh * SQ + q0, mb);
        }
        // wait for TMA completion (phase parity = j & 1)
        {
            uint32_t ph = (uint32_t)(j & 1);
            asm volatile(
                "{\n\t"
                ".reg .pred P;\n\t"
                "WL%=:\n\t"
                "mbarrier.try_wait.parity.acquire.cta.shared::cta.b64 P, [%0], %1, 0x989680;\n\t"
                "@P bra WD%=;\n\t"
                "bra WL%=;\n\t"
                "WD%=:\n\t"
                "}"
                :: "r"(mb), "r"(ph) : "memory");
        }

        // S = Q . K^T  (m16 x n32, k=64); K frags from swizzled smem + cvt
        float s[4][4];
        #pragma unroll
        for (int f = 0; f < 4; f++)
            #pragma unroll
            for (int e = 0; e < 4; e++) s[f][e] = 0.f;
        #pragma unroll
        for (int kk = 0; kk < 8; kk++) {
            const float* kbase = sK2[kk >> 2];
            const int c32 = (kk & 3) * 8 + q4;
            #pragma unroll
            for (int f = 0; f < 4; f++) {
                int key = f * 8 + r4;
                uint32_t b2[2] = { f2tf(kbase[SWZ(key, c32)]),
                                   f2tf(kbase[SWZ(key, c32 + 4)]) };
                mma8(s[f], qf[kk], b2);
            }
        }

        // scale + residual (LDS from TMA tile), write res_out pre-mask, + mask
        #pragma unroll
        for (int f = 0; f < 4; f++) {
            int c = f * 8 + 2 * q4;
            float2 r0v = *(const float2*)&sR[SWZ(lr0, c)];
            float2 r8v = *(const float2*)&sR[SWZ(lr0 + 8, c)];
            s[f][0] = s[f][0] * SCALE + r0v.x;
            s[f][1] = s[f][1] * SCALE + r0v.y;
            s[f][2] = s[f][2] * SCALE + r8v.x;
            s[f][3] = s[f][3] * SCALE + r8v.y;
            int col = kb + c;
            __stcs((float2*)&res_out[res0 + col], make_float2(s[f][0], s[f][1]));
            __stcs((float2*)&res_out[res8 + col], make_float2(s[f][2], s[f][3]));
            float2 mk = *(const float2*)&mrk[col];
            s[f][0] += mk.x; s[f][1] += mk.y;
            s[f][2] += mk.x; s[f][3] += mk.y;
        }

        // online softmax (rows within a quad: shfl xor 1,2)
        float cmax0 = -1e30f, cmax1 = -1e30f;
        #pragma unroll
        for (int f = 0; f < 4; f++) {
            cmax0 = fmaxf(cmax0, fmaxf(s[f][0], s[f][1]));
            cmax1 = fmaxf(cmax1, fmaxf(s[f][2], s[f][3]));
        }
        cmax0 = fmaxf(cmax0, __shfl_xor_sync(0xffffffff, cmax0, 1));
        cmax0 = fmaxf(cmax0, __shfl_xor_sync(0xffffffff, cmax0, 2));
        cmax1 = fmaxf(cmax1, __shfl_xor_sync(0xffffffff, cmax1, 1));
        cmax1 = fmaxf(cmax1, __shfl_xor_sync(0xffffffff, cmax1, 2));
        float nm0 = fmaxf(mrow0, cmax0);
        float nm1 = fmaxf(mrow1, cmax1);
        float corr0 = __expf(mrow0 - nm0);
        float corr1 = __expf(mrow1 - nm1);
        mrow0 = nm0; mrow1 = nm1;

        float sum0 = 0.f, sum1 = 0.f;
        #pragma unroll
        for (int f = 0; f < 4; f++) {
            s[f][0] = __expf(s[f][0] - nm0);
            s[f][1] = __expf(s[f][1] - nm0);
            s[f][2] = __expf(s[f][2] - nm1);
            s[f][3] = __expf(s[f][3] - nm1);
            sum0 += s[f][0] + s[f][1];
            sum1 += s[f][2] + s[f][3];
        }
        sum0 += __shfl_xor_sync(0xffffffff, sum0, 1);
        sum0 += __shfl_xor_sync(0xffffffff, sum0, 2);
        sum1 += __shfl_xor_sync(0xffffffff, sum1, 1);
        sum1 += __shfl_xor_sync(0xffffffff, sum1, 2);
        lrow0 = lrow0 * corr0 + sum0;
        lrow1 = lrow1 * corr1 + sum1;
        #pragma unroll
        for (int f = 0; f < 8; f++) {
            Oacc[f][0] *= corr0; Oacc[f][1] *= corr0;
            Oacc[f][2] *= corr1; Oacc[f][3] *= corr1;
        }

        // O += P . V : A-frags direct from QK C regs (key-permuted to match C);
        // V frags from swizzled smem + cvt (conflict-free LDS.32 pattern)
        #pragma unroll
        for (int kk = 0; kk < 4; kk++) {
            uint32_t a[4] = { f2tf(s[kk][0]), f2tf(s[kk][2]),
                              f2tf(s[kk][1]), f2tf(s[kk][3]) };
            const int kr = kk * 8 + 2 * q4;
            #pragma unroll
            for (int f = 0; f < 8; f++) {
                const float* vbase = sV2[f >> 2];
                const int c32 = (f & 3) * 8 + r4;
                uint32_t b2[2] = { f2tf(vbase[SWZ(kr, c32)]),
                                   f2tf(vbase[SWZ(kr + 1, c32)]) };
                mma8(Oacc[f], a, b2);
            }
        }
    }

    // Epilogue: O / l, store ctx [B, S, H*Dh]
    float inv0 = 1.f / lrow0;
    float inv1 = 1.f / lrow1;
    int row0 = q0 + warp * 16 + r4;
    #pragma unroll
    for (int f = 0; f < 8; f++) {
        int dh = f * 8 + 2 * q4;
        size_t i0 = ((size_t)b * SQ + row0) * DM + h * DH + dh;
        size_t i8 = ((size_t)b * SQ + row0 + 8) * DM + h * DH + dh;
        *(float2*)&ctx_out[i0] = make_float2(Oacc[f][0] * inv0, Oacc[f][1] * inv0);
        *(float2*)&ctx_out[i8] = make_float2(Oacc[f][2] * inv1, Oacc[f][3] * inv1);
    }
}

// ---------------------------------------------------------------------------
// Host
// ---------------------------------------------------------------------------
typedef CUresult (*tEncodeTiled)(
    CUtensorMap*, CUtensorMapDataType, cuuint32_t, void*,
    const cuuint64_t*, const cuuint64_t*, const cuuint32_t*, const cuuint32_t*,
    CUtensorMapInterleave, CUtensorMapSwizzle, CUtensorMapL2promotion,
    CUtensorMapFloatOOBfill);

static void encode_2d(tEncodeTiled fn, CUtensorMap* m, void* ptr,
                      uint64_t d0, uint64_t d1, uint64_t stride1_bytes,
                      uint32_t b0, uint32_t b1) {
    cuuint64_t dims[2]    = {d0, d1};
    cuuint64_t strides[1] = {stride1_bytes};
    cuuint32_t box[2]     = {b0, b1};
    cuuint32_t es[2]      = {1, 1};
    fn(m, CU_TENSOR_MAP_DATA_TYPE_FLOAT32, 2, ptr, dims, strides, box, es,
       CU_TENSOR_MAP_INTERLEAVE_NONE, CU_TENSOR_MAP_SWIZZLE_128B,
       CU_TENSOR_MAP_L2_PROMOTION_L2_128B, CU_TENSOR_MAP_FLOAT_OOB_FILL_NONE);
}

extern "C" void kernel_launch(void* const* d_in, const int* in_sizes, int n_in,
                              void* d_out, int out_size) {
    const float* X    = (const float*)d_in[0];
    const float* mask = (const float*)d_in[1];
    const float* res  = (const float*)d_in[2];
    const float* Wq   = (const float*)d_in[3];
    const float* bq   = (const float*)d_in[4];
    const float* Wk   = (const float*)d_in[5];
    const float* bk   = (const float*)d_in[6];
    const float* Wv   = (const float*)d_in[7];
    const float* bv   = (const float*)d_in[8];

    float* ctx     = (float*)d_out;
    float* res_out = (float*)d_out + (size_t)NB * SQ * DM;

    tEncodeTiled fn = nullptr;
    cudaDriverEntryPointQueryResult qres;
    cudaGetDriverEntryPoint("cuTensorMapEncodeTiled", (void**)&fn,
                            cudaEnableDefault, &qres);

    void* gk = nullptr;
    void* gv = nullptr;
    cudaGetSymbolAddress(&gk, g_k);
    cudaGetSymbolAddress(&gv, g_v);

    CUtensorMap mk, mv, mr;
    encode_2d(fn, &mk, gk, DH, (uint64_t)NB * NH * SQ, DH * 4, 32, 32);
    encode_2d(fn, &mv, gv, DH, (uint64_t)NB * NH * SQ, DH * 4, 32, 32);
    encode_2d(fn, &mr, (void*)res, SQ, (uint64_t)NB * NH * SQ, SQ * 4, 32, 64);

    dim3 g1(DM / 64, (NB * SQ) / 128);
    qkv_kernel<<<g1, 512>>>(X, Wq, bq, Wk, bk, Wv, bv);

    dim3 g2(SQ / 64, NH, NB);
    attn_kernel<<<g2, 128>>>(mk, mv, mr, mask, ctx, res_out);
}

// round 15
// speedup vs baseline: 1.5921x; 1.0897x over previous
#include <cuda_runtime.h>
#include <cuda.h>
#include <cstdint>

#define NB 2
#define NH 12
#define SQ 2048
#define DH 64
#define DM 768
#define SCALE 0.125f

// Scratch for Q/K/V in [B, H, S, Dh] layout, PRE-ROUNDED to tf32 bit patterns
// (attn consumes these only as mma operands -> bitwise-identical results).
__device__ float g_q[NB * NH * SQ * DH];
__device__ float g_k[NB * NH * SQ * DH];
__device__ float g_v[NB * NH * SQ * DH];

__device__ __forceinline__ uint32_t f2tf(float f) {
    uint32_t u;
    asm("cvt.rna.tf32.f32 %0, %1;" : "=r"(u) : "f"(f));
    return u;
}

__device__ __forceinline__ uint4 cvt4(float4 v) {
    return make_uint4(f2tf(v.x), f2tf(v.y), f2tf(v.z), f2tf(v.w));
}

__device__ __forceinline__ void mma8(float* c, const uint32_t* a, const uint32_t* b) {
    asm volatile(
        "mma.sync.aligned.m16n8k8.row.col.f32.tf32.tf32.f32 "
        "{%0,%1,%2,%3}, {%4,%5,%6,%7}, {%8,%9}, {%0,%1,%2,%3};\n"
        : "+f"(c[0]), "+f"(c[1]), "+f"(c[2]), "+f"(c[3])
        : "r"(a[0]), "r"(a[1]), "r"(a[2]), "r"(a[3]), "r"(b[0]), "r"(b[1]));
}

// word-index swizzle inside a SW128 tile with 128B rows (32 f32 words/row)
#define SWZ(r, c) ((r) * 32 + ((c) ^ (4 * ((r) & 7))))

__device__ __forceinline__ void tma_load_2d(uint32_t dst, const CUtensorMap* map,
                                            int cx, int cy, uint32_t mbar) {
    asm volatile(
        "cp.async.bulk.tensor.2d.shared::cta.global.tile.mbarrier::complete_tx::bytes "
        "[%0], [%1, {%2, %3}], [%4];"
        :: "r"(dst), "l"(map), "r"(cx), "r"(cy), "r"(mbar) : "memory");
}

// ---------------------------------------------------------------------------
// Kernel 1: fused QKV projection (R5 split version). ONLY change: epilogue
// stores tf32-ROUNDED values (bits identical to what attn previously produced
// with its per-use cvt) -> attn needs zero cvt for Q/K/V fragments.
// ---------------------------------------------------------------------------
__global__ __launch_bounds__(256) void qkv_kernel(
    const float* __restrict__ X,
    const float* __restrict__ Wq, const float* __restrict__ bq,
    const float* __restrict__ Wk, const float* __restrict__ bk,
    const float* __restrict__ Wv, const float* __restrict__ bv)
{
    const float* W;
    const float* bias;
    float* out;
    if (blockIdx.z == 0)      { W = Wq; bias = bq; out = g_q; }
    else if (blockIdx.z == 1) { W = Wk; bias = bk; out = g_k; }
    else                      { W = Wv; bias = bv; out = g_v; }

    __shared__ uint32_t As[128][36];
    __shared__ uint32_t Bs[64][36];

    const int tid  = threadIdx.x;
    const int lane = tid & 31;
    const int warp = tid >> 5;
    const int wm   = warp >> 1;
    const int wn   = warp & 1;
    const int m0   = blockIdx.y * 128;
    const int n0   = blockIdx.x * 64;

    float acc[2][4][4];
    #pragma unroll
    for (int i = 0; i < 2; i++)
        #pragma unroll
        for (int j = 0; j < 4; j++)
            #pragma unroll
            for (int e = 0; e < 4; e++) acc[i][j][e] = 0.f;

    const int ar = tid >> 3;
    const int ac = (tid & 7) * 4;

    for (int kt = 0; kt < DM / 32; kt++) {
        const int k0 = kt * 32;
        #pragma unroll
        for (int it = 0; it < 4; it++) {
            int r = ar + it * 32;
            float4 v = *(const float4*)&X[(size_t)(m0 + r) * DM + k0 + ac];
            *(uint4*)&As[r][ac] = cvt4(v);
        }
        #pragma unroll
        for (int it = 0; it < 2; it++) {
            int r = ar + it * 32;
            float4 v = *(const float4*)&W[(size_t)(n0 + r) * DM + k0 + ac];
            *(uint4*)&Bs[r][ac] = cvt4(v);
        }
        __syncthreads();
        #pragma unroll
        for (int kk = 0; kk < 4; kk++) {
            uint32_t a[2][4], b[4][2];
            #pragma unroll
            for (int i = 0; i < 2; i++) {
                int r = wm * 32 + i * 16 + (lane >> 2);
                int c = kk * 8 + (lane & 3);
                a[i][0] = As[r][c];
                a[i][1] = As[r + 8][c];
                a[i][2] = As[r][c + 4];
                a[i][3] = As[r + 8][c + 4];
            }
            #pragma unroll
            for (int j = 0; j < 4; j++) {
                int cc = wn * 32 + j * 8 + (lane >> 2);
                int c  = kk * 8 + (lane & 3);
                b[j][0] = Bs[cc][c];
                b[j][1] = Bs[cc][c + 4];
            }
            #pragma unroll
            for (int i = 0; i < 2; i++)
                #pragma unroll
                for (int j = 0; j < 4; j++)
                    mma8(acc[i][j], a[i], b[j]);
        }
        __syncthreads();
    }

    #pragma unroll
    for (int i = 0; i < 2; i++) {
        #pragma unroll
        for (int j = 0; j < 4; j++) {
            int n  = n0 + wn * 32 + j * 8 + 2 * (lane & 3);
            int h  = n >> 6;
            int dh = n & 63;
            float b0 = bias[n], b1 = bias[n + 1];
            #pragma unroll
            for (int rr = 0; rr < 2; rr++) {
                int m  = m0 + wm * 32 + i * 16 + (lane >> 2) + rr * 8;
                int bb = m >> 11;
                int s  = m & 2047;
                size_t idx = (((size_t)(bb * NH + h)) * SQ + s) * DH + dh;
                // store PRE-ROUNDED tf32 bits (same bits attn's cvt produced)
                out[idx]     = __uint_as_float(f2tf(acc[i][j][rr * 2 + 0] + b0));
                out[idx + 1] = __uint_as_float(f2tf(acc[i][j][rr * 2 + 1] + b1));
            }
        }
    }
}

// ---------------------------------------------------------------------------
// Kernel 2: flash attention + RealFormer residual (EXACT R8 structure).
// ONLY change vs R8: Q/K/V fragments are raw pre-rounded bits -> NO per-use
// cvt (-128 cvt/thread/chunk, ~27% of the instruction stream).
// Single-buffer TMA, SW128 smem tiles, PV A-frags direct from QK C registers,
// CTA = 128 threads / 64 q-rows, 4 CTAs/SM.
// ---------------------------------------------------------------------------
__global__ __launch_bounds__(128, 4) void attn_kernel(
    const __grid_constant__ CUtensorMap mapK,
    const __grid_constant__ CUtensorMap mapV,
    const __grid_constant__ CUtensorMap mapR,
    const float* __restrict__ mask,
    float* __restrict__ ctx_out,
    float* __restrict__ res_out)
{
    __shared__ __align__(1024) float sK2[2][1024];   // two [32 key x 32 dh] SW128 tiles
    __shared__ __align__(1024) float sV2[2][1024];   // two [32 key x 32 dh] SW128 tiles
    __shared__ __align__(1024) float sR[2048];       // [64 q x 32 k] SW128 tile
    __shared__ uint64_t mbar;

    const int tid  = threadIdx.x;
    const int lane = tid & 31;
    const int warp = tid >> 5;          // 0..3
    const int q4   = lane & 3;
    const int r4   = lane >> 2;
    const int h  = blockIdx.y;
    const int b  = blockIdx.z;
    const int bh = b * NH + h;
    const int q0 = blockIdx.x * 64;

    const uint32_t mb = (uint32_t)__cvta_generic_to_shared(&mbar);
    const uint32_t sK0a = (uint32_t)__cvta_generic_to_shared(&sK2[0][0]);
    const uint32_t sK1a = (uint32_t)__cvta_generic_to_shared(&sK2[1][0]);
    const uint32_t sV0a = (uint32_t)__cvta_generic_to_shared(&sV2[0][0]);
    const uint32_t sV1a = (uint32_t)__cvta_generic_to_shared(&sV2[1][0]);
    const uint32_t sRa  = (uint32_t)__cvta_generic_to_shared(&sR[0]);

    if (tid == 0) {
        asm volatile("mbarrier.init.shared.b64 [%0], 1;" :: "r"(mb) : "memory");
    }
    __syncthreads();

    const float* Q = g_q + (size_t)bh * SQ * DH;

    // Q fragments: raw pre-rounded bits, no cvt
    uint32_t qf[8][4];
    {
        int r0 = q0 + warp * 16 + r4;
        const uint32_t* Qr0 = (const uint32_t*)(Q + (size_t)r0 * DH);
        const uint32_t* Qr8 = Qr0 + 8 * DH;
        #pragma unroll
        for (int kk = 0; kk < 8; kk++) {
            int c = kk * 8 + q4;
            qf[kk][0] = Qr0[c];
            qf[kk][1] = Qr8[c];
            qf[kk][2] = Qr0[c + 4];
            qf[kk][3] = Qr8[c + 4];
        }
    }

    float Oacc[8][4];
    #pragma unroll
    for (int f = 0; f < 8; f++)
        #pragma unroll
        for (int e = 0; e < 4; e++) Oacc[f][e] = 0.f;
    float mrow0 = -1e30f, mrow1 = -1e30f;
    float lrow0 = 0.f, lrow1 = 0.f;

    const int rq0 = q0 + warp * 16 + r4;
    const size_t res0 = ((size_t)bh * SQ + rq0) * SQ;
    const size_t res8 = res0 + (size_t)8 * SQ;
    const float* mrk = mask + b * SQ;
    const int lr0 = warp * 16 + r4;     // local row in sR

    for (int j = 0; j < SQ / 32; j++) {
        const int kb = j * 32;
        __syncthreads();   // all warps done reading previous chunk's tiles

        if (tid == 0) {
            const int rowKV = bh * SQ + kb;
            asm volatile("mbarrier.arrive.expect_tx.shared.b64 _, [%0], %1;"
                         :: "r"(mb), "r"(24576u) : "memory");
            tma_load_2d(sK0a, &mapK, 0,  rowKV, mb);
            tma_load_2d(sK1a, &mapK, 32, rowKV, mb);
            tma_load_2d(sV0a, &mapV, 0,  rowKV, mb);
            tma_load_2d(sV1a, &mapV, 32, rowKV, mb);
            tma_load_2d(sRa,  &mapR, kb, bh * SQ + q0, mb);
        }
        // wait for TMA completion (phase parity = j & 1)
        {
            uint32_t ph = (uint32_t)(j & 1);
            asm volatile(
                "{\n\t"
                ".reg .pred P;\n\t"
                "WL%=:\n\t"
                "mbarrier.try_wait.parity.acquire.cta.shared::cta.b64 P, [%0], %1, 0x989680;\n\t"
                "@P bra WD%=;\n\t"
                "bra WL%=;\n\t"
                "WD%=:\n\t"
                "}"
                :: "r"(mb), "r"(ph) : "memory");
        }

        // S = Q . K^T  (m16 x n32, k=64); K frags: raw bits, no cvt
        float s[4][4];
        #pragma unroll
        for (int f = 0; f < 4; f++)
            #pragma unroll
            for (int e = 0; e < 4; e++) s[f][e] = 0.f;
        #pragma unroll
        for (int kk = 0; kk < 8; kk++) {
            const uint32_t* kbase = (const uint32_t*)sK2[kk >> 2];
            const int c32 = (kk & 3) * 8 + q4;
            #pragma unroll
            for (int f = 0; f < 4; f++) {
                int key = f * 8 + r4;
                uint32_t b2[2] = { kbase[SWZ(key, c32)],
                                   kbase[SWZ(key, c32 + 4)] };
                mma8(s[f], qf[kk], b2);
            }
        }

        // scale + residual (LDS from TMA tile), write res_out pre-mask, + mask
        #pragma unroll
        for (int f = 0; f < 4; f++) {
            int c = f * 8 + 2 * q4;
            float2 r0v = *(const float2*)&sR[SWZ(lr0, c)];
            float2 r8v = *(const float2*)&sR[SWZ(lr0 + 8, c)];
            s[f][0] = s[f][0] * SCALE + r0v.x;
            s[f][1] = s[f][1] * SCALE + r0v.y;
            s[f][2] = s[f][2] * SCALE + r8v.x;
            s[f][3] = s[f][3] * SCALE + r8v.y;
            int col = kb + c;
            __stcs((float2*)&res_out[res0 + col], make_float2(s[f][0], s[f][1]));
            __stcs((float2*)&res_out[res8 + col], make_float2(s[f][2], s[f][3]));
            float2 mk = *(const float2*)&mrk[col];
            s[f][0] += mk.x; s[f][1] += mk.y;
            s[f][2] += mk.x; s[f][3] += mk.y;
        }

        // online softmax (rows within a quad: shfl xor 1,2)
        float cmax0 = -1e30f, cmax1 = -1e30f;
        #pragma unroll
        for (int f = 0; f < 4; f++) {
            cmax0 = fmaxf(cmax0, fmaxf(s[f][0], s[f][1]));
            cmax1 = fmaxf(cmax1, fmaxf(s[f][2], s[f][3]));
        }
        cmax0 = fmaxf(cmax0, __shfl_xor_sync(0xffffffff, cmax0, 1));
        cmax0 = fmaxf(cmax0, __shfl_xor_sync(0xffffffff, cmax0, 2));
        cmax1 = fmaxf(cmax1, __shfl_xor_sync(0xffffffff, cmax1, 1));
        cmax1 = fmaxf(cmax1, __shfl_xor_sync(0xffffffff, cmax1, 2));
        float nm0 = fmaxf(mrow0, cmax0);
        float nm1 = fmaxf(mrow1, cmax1);
        float corr0 = __expf(mrow0 - nm0);
        float corr1 = __expf(mrow1 - nm1);
        mrow0 = nm0; mrow1 = nm1;

        float sum0 = 0.f, sum1 = 0.f;
        #pragma unroll
        for (int f = 0; f < 4; f++) {
            s[f][0] = __expf(s[f][0] - nm0);
            s[f][1] = __expf(s[f][1] - nm0);
            s[f][2] = __expf(s[f][2] - nm1);
            s[f][3] = __expf(s[f][3] - nm1);
            sum0 += s[f][0] + s[f][1];
            sum1 += s[f][2] + s[f][3];
        }
        sum0 += __shfl_xor_sync(0xffffffff, sum0, 1);
        sum0 += __shfl_xor_sync(0xffffffff, sum0, 2);
        sum1 += __shfl_xor_sync(0xffffffff, sum1, 1);
        sum1 += __shfl_xor_sync(0xffffffff, sum1, 2);
        lrow0 = lrow0 * corr0 + sum0;
        lrow1 = lrow1 * corr1 + sum1;
        #pragma unroll
        for (int f = 0; f < 8; f++) {
            Oacc[f][0] *= corr0; Oacc[f][1] *= corr0;
            Oacc[f][2] *= corr1; Oacc[f][3] *= corr1;
        }

        // O += P . V : A-frags from QK C regs (cvt needed: P is computed);
        // V frags: raw bits, no cvt
        #pragma unroll
        for (int kk = 0; kk < 4; kk++) {
            uint32_t a[4] = { f2tf(s[kk][0]), f2tf(s[kk][2]),
                              f2tf(s[kk][1]), f2tf(s[kk][3]) };
            const int kr = kk * 8 + 2 * q4;
            #pragma unroll
            for (int f = 0; f < 8; f++) {
                const uint32_t* vbase = (const uint32_t*)sV2[f >> 2];
                const int c32 = (f & 3) * 8 + r4;
                uint32_t b2[2] = { vbase[SWZ(kr, c32)],
                                   vbase[SWZ(kr + 1, c32)] };
                mma8(Oacc[f], a, b2);
            }
        }
    }

    // Epilogue: O / l, store ctx [B, S, H*Dh]
    float inv0 = 1.f / lrow0;
    float inv1 = 1.f / lrow1;
    int row0 = q0 + warp * 16 + r4;
    #pragma unroll
    for (int f = 0; f < 8; f++) {
        int dh = f * 8 + 2 * q4;
        size_t i0 = ((size_t)b * SQ + row0) * DM + h * DH + dh;
        size_t i8 = ((size_t)b * SQ + row0 + 8) * DM + h * DH + dh;
        *(float2*)&ctx_out[i0] = make_float2(Oacc[f][0] * inv0, Oacc[f][1] * inv0);
        *(float2*)&ctx_out[i8] = make_float2(Oacc[f][2] * inv1, Oacc[f][3] * inv1);
    }
}

// ---------------------------------------------------------------------------
// Host
// ---------------------------------------------------------------------------
typedef CUresult (*tEncodeTiled)(
    CUtensorMap*, CUtensorMapDataType, cuuint32_t, void*,
    const cuuint64_t*, const cuuint64_t*, const cuuint32_t*, const cuuint32_t*,
    CUtensorMapInterleave, CUtensorMapSwizzle, CUtensorMapL2promotion,
    CUtensorMapFloatOOBfill);

static void encode_2d(tEncodeTiled fn, CUtensorMap* m, void* ptr,
                      uint64_t d0, uint64_t d1, uint64_t stride1_bytes,
                      uint32_t b0, uint32_t b1) {
    cuuint64_t dims[2]    = {d0, d1};
    cuuint64_t strides[1] = {stride1_bytes};
    cuuint32_t box[2]     = {b0, b1};
    cuuint32_t es[2]      = {1, 1};
    fn(m, CU_TENSOR_MAP_DATA_TYPE_FLOAT32, 2, ptr, dims, strides, box, es,
       CU_TENSOR_MAP_INTERLEAVE_NONE, CU_TENSOR_MAP_SWIZZLE_128B,
       CU_TENSOR_MAP_L2_PROMOTION_L2_128B, CU_TENSOR_MAP_FLOAT_OOB_FILL_NONE);
}

extern "C" void kernel_launch(void* const* d_in, const int* in_sizes, int n_in,
                              void* d_out, int out_size) {
    const float* X    = (const float*)d_in[0];
    const float* mask = (const float*)d_in[1];
    const float* res  = (const float*)d_in[2];
    const float* Wq   = (const float*)d_in[3];
    const float* bq   = (const float*)d_in[4];
    const float* Wk   = (const float*)d_in[5];
    const float* bk   = (const float*)d_in[6];
    const float* Wv   = (const float*)d_in[7];
    const float* bv   = (const float*)d_in[8];

    float* ctx     = (float*)d_out;
    float* res_out = (float*)d_out + (size_t)NB * SQ * DM;

    tEncodeTiled fn = nullptr;
    cudaDriverEntryPointQueryResult qres;
    cudaGetDriverEntryPoint("cuTensorMapEncodeTiled", (void**)&fn,
                            cudaEnableDefault, &qres);

    void* gk = nullptr;
    void* gv = nullptr;
    cudaGetSymbolAddress(&gk, g_k);
    cudaGetSymbolAddress(&gv, g_v);

    CUtensorMap mk, mv, mr;
    encode_2d(fn, &mk, gk, DH, (uint64_t)NB * NH * SQ, DH * 4, 32, 32);
    encode_2d(fn, &mv, gv, DH, (uint64_t)NB * NH * SQ, DH * 4, 32, 32);
    encode_2d(fn, &mr, (void*)res, SQ, (uint64_t)NB * NH * SQ, SQ * 4, 32, 64);

    dim3 g1(DM / 64, (NB * SQ) / 128, 3);
    qkv_kernel<<<g1, 256>>>(X, Wq, bq, Wk, bk, Wv, bv);

    dim3 g2(SQ / 64, NH, NB);
    attn_kernel<<<g2, 128>>>(mk, mv, mr, mask, ctx, res_out);
}